// round 12
// baseline (speedup 1.0000x reference)
#include <cuda_runtime.h>

#define BB 8192
#define MM 16
#define NN 256
#define CC 64
#define PITCH 66
#define NBLK 296
#define NTILES 2048   /* (BB/64) * MM */

typedef unsigned long long ull;

// Packed fp32x2 FMA (Blackwell sm_103a; only reachable via PTX)
__device__ __forceinline__ void ffma2(ull &d, ull a, ull b) {
    asm("fma.rn.f32x2 %0, %1, %2, %0;" : "+l"(d) : "l"(a), "l"(b));
}

__global__ __launch_bounds__(256, 1)
void fq_kernel(const float* __restrict__ inp, const float* __restrict__ cb,
               float* __restrict__ codes, float* __restrict__ idx_out, int write_idx)
{
    extern __shared__ float smem[];
    float* cbs = smem;                       // 256 x PITCH  (codebook[m], pitch-padded)
    float* xs  = smem + NN * PITCH;          // 64  x PITCH  (input tile)
    float* c2s = xs + 64 * PITCH;            // 256          (||c||^2)

    const int tid  = threadIdx.x;
    const int rgrp = tid >> 5;               // warp id: owns rows rgrp*8 .. +7
    const int lane = tid & 31;               // owns cols lane + 32*j, j<8

    const int t0 = (int)(((long long)blockIdx.x       * NTILES) / NBLK);
    const int t1 = (int)(((long long)(blockIdx.x + 1) * NTILES) / NBLK);

    int prev_m = -1;
    for (int t = t0; t < t1; t++) {
        const int m     = t >> 7;
        const int chunk = t & 127;

        if (m != prev_m) {
            __syncthreads();   // previous tile's reads of cbs/c2s complete
            // Load codebook[m] (16384 floats) coalesced, store pitch-66 rows.
            const float4* cg = (const float4*)(cb + (size_t)m * NN * CC);
            #pragma unroll
            for (int k = 0; k < 16; k++) {
                int i4 = tid + k * 256;
                float4 v = cg[i4];
                int e = i4 * 4;
                int n = e >> 6, c = e & 63;
                float* dst = cbs + n * PITCH + c;
                *(float2*)(dst)     = make_float2(v.x, v.y);
                *(float2*)(dst + 2) = make_float2(v.z, v.w);
            }
            __syncthreads();
            {   // ||c||^2 per codeword; thread tid handles codeword tid
                const float* p = cbs + tid * PITCH;
                float s = 0.f;
                #pragma unroll
                for (int c = 0; c < CC; c++) s = fmaf(p[c], p[c], s);
                c2s[tid] = s;
            }
            prev_m = m;
        }

        __syncthreads();   // prior compute done before overwriting xs; c2s visible
        {   // Load x tile: 64 rows x 64 floats.
            // 256 threads: 4 threads per row, 16 floats (4x float4) each.
            int row = tid >> 2;              // 0..63
            int c0  = (tid & 3) * 16;        // 0,16,32,48
            const float* xg = inp + ((size_t)(chunk * 64 + row) * MM + m) * CC + c0;
            float* dst = xs + row * PITCH + c0;
            #pragma unroll
            for (int q = 0; q < 4; q++) {
                float4 v = *(const float4*)(xg + q * 4);
                *(float2*)(dst + q * 4)     = make_float2(v.x, v.y);
                *(float2*)(dst + q * 4 + 2) = make_float2(v.z, v.w);
            }
        }
        __syncthreads();

        // 8x8 register tile; accumulator lanes split over (even c, odd c).
        ull acc[8][8];
        #pragma unroll
        for (int i = 0; i < 8; i++)
            #pragma unroll
            for (int j = 0; j < 8; j++) acc[i][j] = 0ull;

        const float* xrow  = xs  + (rgrp * 8) * PITCH;
        const float* cbase = cbs + lane * PITCH;

        #pragma unroll 4
        for (int cp = 0; cp < 32; cp++) {
            const int c = cp * 2;
            ull xv[8], cv[8];
            #pragma unroll
            for (int i = 0; i < 8; i++)
                xv[i] = *(const ull*)(xrow + i * PITCH + c);      // LDS.64 broadcast
            #pragma unroll
            for (int j = 0; j < 8; j++)
                cv[j] = *(const ull*)(cbase + (j * 32) * PITCH + c); // LDS.64, ~CF
            #pragma unroll
            for (int i = 0; i < 8; i++)
                #pragma unroll
                for (int j = 0; j < 8; j++)
                    ffma2(acc[i][j], xv[i], cv[j]);
        }

        // argmin over n per row: dist = ||c||^2 - 2*dot  (x^2 constant per row)
        int bn[8];
        #pragma unroll
        for (int i = 0; i < 8; i++) {
            float bestv = __int_as_float(0x7f800000);  // +inf
            int   bestn = NN;
            #pragma unroll
            for (int j = 0; j < 8; j++) {
                float2 p = *(float2*)&acc[i][j];
                float dot = p.x + p.y;
                int n = lane + j * 32;
                float d = fmaf(-2.f, dot, c2s[n]);
                if (d < bestv) { bestv = d; bestn = n; }  // j ascending => first-min
            }
            #pragma unroll
            for (int o = 16; o > 0; o >>= 1) {
                float ov = __shfl_xor_sync(0xffffffffu, bestv, o);
                int   on = __shfl_xor_sync(0xffffffffu, bestn, o);
                if (ov < bestv || (ov == bestv && on < bestn)) { bestv = ov; bestn = on; }
            }
            bn[i] = bestn;
        }

        // Gather codes (codebook is L2-hot) + write idx AS FLOAT (d_out is f32)
        const size_t b0 = (size_t)chunk * 64 + rgrp * 8;
        #pragma unroll
        for (int i = 0; i < 8; i++) {
            const float2* src = (const float2*)(cb + ((size_t)m * NN + bn[i]) * CC);
            float2 v = __ldg(src + lane);
            ((float2*)(codes + ((b0 + i) * MM + m) * CC))[lane] = v;
        }
        if (write_idx && lane == 0) {
            #pragma unroll
            for (int i = 0; i < 8; i++)
                idx_out[(b0 + i) * MM + m] = (float)bn[i];   // numeric value, not bit pattern
        }
    }
}

extern "C" void kernel_launch(void* const* d_in, const int* in_sizes, int n_in,
                              void* d_out, int out_size) {
    const float* inp = (const float*)d_in[0];   // [B, M, C] f32
    const float* cb  = (const float*)d_in[1];   // [M, N, C] f32
    float* codes = (float*)d_out;
    float* idx_o = (float*)d_out + (size_t)BB * MM * CC;
    const int write_idx = (out_size >= BB * MM * CC + BB * MM) ? 1 : 0;

    const int smem_bytes = (NN * PITCH + 64 * PITCH + NN) * 4;  // 85504
    cudaFuncSetAttribute(fq_kernel, cudaFuncAttributeMaxDynamicSharedMemorySize, smem_bytes);
    fq_kernel<<<NBLK, 256, smem_bytes>>>(inp, cb, codes, idx_o, write_idx);
}

// round 13
// speedup vs baseline: 1.6437x; 1.6437x over previous
#include <cuda_runtime.h>

#define BB 8192
#define MM 16
#define NN 256
#define CC 64
#define NBLK 296
#define NTILES 2048   /* (BB/64) * MM */

#define SCB 257   /* codebook row stride in float2 (32 rows of 256 + pad) */
#define SXS 65    /* x-tile  row stride in float2 (32 rows of 64  + pad) */

typedef unsigned long long ull;

// Packed fp32x2 FMA (Blackwell sm_103a; only reachable via PTX)
__device__ __forceinline__ void ffma2(ull &d, ull a, ull b) {
    asm("fma.rn.f32x2 %0, %1, %2, %0;" : "+l"(d) : "l"(a), "l"(b));
}

__global__ __launch_bounds__(256, 1)
void fq_kernel(const float* __restrict__ inp, const float* __restrict__ cb,
               float* __restrict__ codes, float* __restrict__ idx_out, int write_idx)
{
    extern __shared__ float2 sm2[];
    float2* cbp = sm2;                    // [32][SCB]  codebook pairs: cbp[cp][n] = (cb[n][2cp], cb[n][2cp+1])
    float2* xsp = sm2 + 32 * SCB;         // [32][SXS]  x pairs:        xsp[cp][row]
    float*  c2s = (float*)(sm2 + 32 * SCB + 32 * SXS);   // 256  ||c||^2

    const int tid  = threadIdx.x;
    const int rgrp = tid >> 5;            // warp id: owns rows rgrp*8 .. +7
    const int lane = tid & 31;            // owns cols lane + 32*j, j<8

    const int t0 = (int)(((long long)blockIdx.x       * NTILES) / NBLK);
    const int t1 = (int)(((long long)(blockIdx.x + 1) * NTILES) / NBLK);

    int prev_m = -1;
    for (int t = t0; t < t1; t++) {
        const int m     = t >> 7;
        const int chunk = t & 127;

        if (m != prev_m) {
            __syncthreads();   // previous tile's reads of cbp/c2s complete
            // Load codebook[m] (16384 floats) coalesced; store transposed pairs.
            const float4* cg = (const float4*)(cb + (size_t)m * NN * CC);
            #pragma unroll
            for (int k = 0; k < 16; k++) {
                int i4 = tid + k * 256;
                float4 v = cg[i4];
                int e  = i4 * 4;
                int n  = e >> 6;
                int cp = (e & 63) >> 1;        // even: e%64 in {0,4,...}
                cbp[cp * SCB + n]       = make_float2(v.x, v.y);
                cbp[(cp + 1) * SCB + n] = make_float2(v.z, v.w);
            }
            __syncthreads();
            {   // ||c||^2 per codeword; thread tid handles codeword tid (CF loads)
                float s = 0.f;
                #pragma unroll
                for (int cp = 0; cp < 32; cp++) {
                    float2 p = cbp[cp * SCB + tid];
                    s = fmaf(p.x, p.x, fmaf(p.y, p.y, s));
                }
                c2s[tid] = s;
            }
            prev_m = m;
        }

        __syncthreads();   // prior compute done before overwriting xsp; c2s visible
        {   // Load x tile: 64 rows x 64 floats; 4 threads/row, 16 floats each.
            int row = tid >> 2;              // 0..63
            int c0  = (tid & 3) * 16;        // 0,16,32,48
            const float* xg = inp + ((size_t)(chunk * 64 + row) * MM + m) * CC + c0;
            int cp0 = c0 >> 1;
            #pragma unroll
            for (int q = 0; q < 4; q++) {
                float4 v = *(const float4*)(xg + q * 4);
                xsp[(cp0 + 2 * q) * SXS + row]     = make_float2(v.x, v.y);
                xsp[(cp0 + 2 * q + 1) * SXS + row] = make_float2(v.z, v.w);
            }
        }
        __syncthreads();

        // 8x8 register tile; accumulator lanes split over (even c, odd c).
        ull acc[8][8];
        #pragma unroll
        for (int i = 0; i < 8; i++)
            #pragma unroll
            for (int j = 0; j < 8; j++) acc[i][j] = 0ull;

        const ull* xbase = (const ull*)(xsp) + rgrp * 8;   // + cp*SXS + i
        const ull* cbase = (const ull*)(cbp) + lane;       // + cp*SCB + 32*j

        #pragma unroll 8
        for (int cp = 0; cp < 32; cp++) {
            ull xv[8], cv[8];
            #pragma unroll
            for (int i = 0; i < 8; i++)
                xv[i] = xbase[cp * SXS + i];           // LDS.64 broadcast
            #pragma unroll
            for (int j = 0; j < 8; j++)
                cv[j] = cbase[cp * SCB + 32 * j];      // LDS.64 conflict-free
            #pragma unroll
            for (int i = 0; i < 8; i++)
                #pragma unroll
                for (int j = 0; j < 8; j++)
                    ffma2(acc[i][j], xv[i], cv[j]);
        }

        // argmin over n per row: dist = ||c||^2 - 2*dot  (x^2 constant per row)
        float c2j[8];
        #pragma unroll
        for (int j = 0; j < 8; j++) c2j[j] = c2s[lane + 32 * j];   // CF

        int bn[8];
        #pragma unroll
        for (int i = 0; i < 8; i++) {
            float bestv = __int_as_float(0x7f800000);  // +inf
            int   bestn = NN;
            #pragma unroll
            for (int j = 0; j < 8; j++) {
                float2 p = *(float2*)&acc[i][j];
                float dot = p.x + p.y;
                float d = fmaf(-2.f, dot, c2j[j]);
                int n = lane + j * 32;
                if (d < bestv) { bestv = d; bestn = n; }  // j ascending => first-min
            }
            #pragma unroll
            for (int o = 16; o > 0; o >>= 1) {
                float ov = __shfl_xor_sync(0xffffffffu, bestv, o);
                int   on = __shfl_xor_sync(0xffffffffu, bestn, o);
                if (ov < bestv || (ov == bestv && on < bestn)) { bestv = ov; bestn = on; }
            }
            bn[i] = bestn;
        }

        // Gather codes (codebook is L2-hot) + write idx AS FLOAT (d_out is f32)
        const size_t b0 = (size_t)chunk * 64 + rgrp * 8;
        #pragma unroll
        for (int i = 0; i < 8; i++) {
            const float2* src = (const float2*)(cb + ((size_t)m * NN + bn[i]) * CC);
            float2 v = __ldg(src + lane);
            ((float2*)(codes + ((b0 + i) * MM + m) * CC))[lane] = v;
        }
        if (write_idx && lane == 0) {
            #pragma unroll
            for (int i = 0; i < 8; i++)
                idx_out[(b0 + i) * MM + m] = (float)bn[i];
        }
    }
}

extern "C" void kernel_launch(void* const* d_in, const int* in_sizes, int n_in,
                              void* d_out, int out_size) {
    const float* inp = (const float*)d_in[0];   // [B, M, C] f32
    const float* cb  = (const float*)d_in[1];   // [M, N, C] f32
    float* codes = (float*)d_out;
    float* idx_o = (float*)d_out + (size_t)BB * MM * CC;
    const int write_idx = (out_size >= BB * MM * CC + BB * MM) ? 1 : 0;

    const int smem_bytes = (32 * SCB + 32 * SXS) * 8 + NN * 4;  // 83456
    cudaFuncSetAttribute(fq_kernel, cudaFuncAttributeMaxDynamicSharedMemorySize, smem_bytes);
    fq_kernel<<<NBLK, 256, smem_bytes>>>(inp, cb, codes, idx_o, write_idx);
}